// round 1
// baseline (speedup 1.0000x reference)
#include <cuda_runtime.h>
#include <math.h>

// Problem constants
#define B_  4
#define S_  2048
#define D_  1024
#define H_  16
#define DK_ 64
#define M_  (B_ * S_)   // 8192 rows

// Scratch buffers (allocation-free rule: __device__ globals)
__device__ float g_Q [M_ * D_];
__device__ float g_K [M_ * D_];
__device__ float g_V [M_ * D_];
__device__ float g_AO[M_ * D_];

// ---------------------------------------------------------------------------
// SGEMM (NT): C[m][n] = sum_k A[m][k] * W[n][k]
// M=8192, N=1024, K=1024. 128x128 block, BK=8, 8x8 per thread, 256 threads.
// ---------------------------------------------------------------------------
__global__ __launch_bounds__(256) void sgemm_nt(const float* __restrict__ A,
                                                const float* __restrict__ W,
                                                float* __restrict__ C)
{
    const int K = D_, N = D_;
    __shared__ float As[8][128];
    __shared__ float Bs[8][128];

    const int t  = threadIdx.x;
    const int bm = blockIdx.y * 128;
    const int bn = blockIdx.x * 128;
    const int tx = t & 15;        // 0..15 -> N direction
    const int ty = t >> 4;        // 0..15 -> M direction
    const int lr = t >> 1;        // load row 0..127
    const int lk = (t & 1) * 4;   // load k offset 0 or 4

    const float* Ap = A + (size_t)(bm + lr) * K + lk;
    const float* Wp = W + (size_t)(bn + lr) * K + lk;

    float acc[8][8];
#pragma unroll
    for (int i = 0; i < 8; i++)
#pragma unroll
        for (int j = 0; j < 8; j++) acc[i][j] = 0.0f;

    for (int k0 = 0; k0 < K; k0 += 8) {
        float4 av = *(const float4*)(Ap + k0);
        float4 wv = *(const float4*)(Wp + k0);
        As[lk + 0][lr] = av.x; As[lk + 1][lr] = av.y;
        As[lk + 2][lr] = av.z; As[lk + 3][lr] = av.w;
        Bs[lk + 0][lr] = wv.x; Bs[lk + 1][lr] = wv.y;
        Bs[lk + 2][lr] = wv.z; Bs[lk + 3][lr] = wv.w;
        __syncthreads();

#pragma unroll
        for (int kk = 0; kk < 8; kk++) {
            float a[8], b[8];
            *(float4*)&a[0] = *(const float4*)&As[kk][ty * 8];
            *(float4*)&a[4] = *(const float4*)&As[kk][ty * 8 + 4];
            *(float4*)&b[0] = *(const float4*)&Bs[kk][tx * 8];
            *(float4*)&b[4] = *(const float4*)&Bs[kk][tx * 8 + 4];
#pragma unroll
            for (int i = 0; i < 8; i++)
#pragma unroll
                for (int j = 0; j < 8; j++) acc[i][j] += a[i] * b[j];
        }
        __syncthreads();
    }

#pragma unroll
    for (int i = 0; i < 8; i++) {
        float* Cp = C + (size_t)(bm + ty * 8 + i) * N + bn + tx * 8;
        *(float4*)(Cp)     = make_float4(acc[i][0], acc[i][1], acc[i][2], acc[i][3]);
        *(float4*)(Cp + 4) = make_float4(acc[i][4], acc[i][5], acc[i][6], acc[i][7]);
    }
}

// ---------------------------------------------------------------------------
// Causal flash attention, fp32.
// One block per (q_tile=64, head, batch). 256 threads = 16x16.
// Thread (tx,ty) owns rows ty*4..+3 and (for S/P) cols tx*4..+3,
// (for O) dk cols tx*4..+3.
// Smem: Qs[d][r] 64x64, Ks[d][c] 64x64, Vs[c][d] 64x64, Ps[r][c] 64x65.
// ---------------------------------------------------------------------------
__global__ __launch_bounds__(256) void attn_kernel(const float* __restrict__ Q,
                                                   const float* __restrict__ K,
                                                   const float* __restrict__ V,
                                                   float* __restrict__ O)
{
    extern __shared__ float sm[];
    float* Qs = sm;               // [64][64], d-major:  Qs[d*64 + r]
    float* Ks = sm + 4096;        // [64][64], d-major:  Ks[d*64 + c]
    float* Vs = sm + 8192;        // [64][64], c-major:  Vs[c*64 + d]
    float* Ps = sm + 12288;       // [64][65], r-major:  Ps[r*65 + c]

    const int qt = blockIdx.x;    // query tile 0..31
    const int h  = blockIdx.y;
    const int b  = blockIdx.z;
    const int t  = threadIdx.x;
    const int tx = t & 15;
    const int ty = t >> 4;

    const size_t headoff = (size_t)h * DK_;
    const float* Qg = Q + ((size_t)(b * S_) + qt * 64) * D_ + headoff;

    // Load Q tile transposed (d-major), pre-scaled by 1/sqrt(DK)=0.125
#pragma unroll
    for (int idx = t; idx < 1024; idx += 256) {
        int r = idx >> 4, d = (idx & 15) << 2;
        float4 v = *(const float4*)(Qg + (size_t)r * D_ + d);
        Qs[(d + 0) * 64 + r] = v.x * 0.125f;
        Qs[(d + 1) * 64 + r] = v.y * 0.125f;
        Qs[(d + 2) * 64 + r] = v.z * 0.125f;
        Qs[(d + 3) * 64 + r] = v.w * 0.125f;
    }

    float o[4][4];
    float mi[4], li[4];
#pragma unroll
    for (int i = 0; i < 4; i++) {
        mi[i] = -INFINITY;
        li[i] = 0.0f;
#pragma unroll
        for (int j = 0; j < 4; j++) o[i][j] = 0.0f;
    }

    for (int kt = 0; kt <= qt; kt++) {
        __syncthreads();  // protect Ks/Vs/Ps readers of previous iter (and Q loads on iter 0)

        const float* Kg = K + ((size_t)(b * S_) + kt * 64) * D_ + headoff;
        const float* Vg = V + ((size_t)(b * S_) + kt * 64) * D_ + headoff;
#pragma unroll
        for (int idx = t; idx < 1024; idx += 256) {
            int r = idx >> 4, d = (idx & 15) << 2;
            float4 kv = *(const float4*)(Kg + (size_t)r * D_ + d);
            Ks[(d + 0) * 64 + r] = kv.x;
            Ks[(d + 1) * 64 + r] = kv.y;
            Ks[(d + 2) * 64 + r] = kv.z;
            Ks[(d + 3) * 64 + r] = kv.w;
            float4 vv = *(const float4*)(Vg + (size_t)r * D_ + d);
            *(float4*)&Vs[r * 64 + d] = vv;
        }
        __syncthreads();

        // S = Q K^T  (4x4 per thread)
        float s[4][4];
#pragma unroll
        for (int i = 0; i < 4; i++)
#pragma unroll
            for (int j = 0; j < 4; j++) s[i][j] = 0.0f;

#pragma unroll 8
        for (int d = 0; d < 64; d++) {
            float4 qv = *(const float4*)&Qs[d * 64 + ty * 4];
            float4 kv = *(const float4*)&Ks[d * 64 + tx * 4];
            float qa[4] = {qv.x, qv.y, qv.z, qv.w};
            float ka[4] = {kv.x, kv.y, kv.z, kv.w};
#pragma unroll
            for (int i = 0; i < 4; i++)
#pragma unroll
                for (int j = 0; j < 4; j++) s[i][j] += qa[i] * ka[j];
        }

        // Causal mask only on the diagonal tile
        if (kt == qt) {
#pragma unroll
            for (int i = 0; i < 4; i++)
#pragma unroll
                for (int j = 0; j < 4; j++)
                    if (tx * 4 + j > ty * 4 + i) s[i][j] = -INFINITY;
        }

        // Online softmax update
#pragma unroll
        for (int i = 0; i < 4; i++) {
            float v = fmaxf(fmaxf(s[i][0], s[i][1]), fmaxf(s[i][2], s[i][3]));
            v = fmaxf(v, __shfl_xor_sync(0xffffffffu, v, 1));
            v = fmaxf(v, __shfl_xor_sync(0xffffffffu, v, 2));
            v = fmaxf(v, __shfl_xor_sync(0xffffffffu, v, 4));
            v = fmaxf(v, __shfl_xor_sync(0xffffffffu, v, 8));
            float mn    = fmaxf(mi[i], v);
            float alpha = __expf(mi[i] - mn);
            mi[i] = mn;
            li[i] *= alpha;
            o[i][0] *= alpha; o[i][1] *= alpha; o[i][2] *= alpha; o[i][3] *= alpha;
            float p0 = __expf(s[i][0] - mn);
            float p1 = __expf(s[i][1] - mn);
            float p2 = __expf(s[i][2] - mn);
            float p3 = __expf(s[i][3] - mn);
            li[i] += (p0 + p1) + (p2 + p3);
            float* pr = &Ps[(ty * 4 + i) * 65 + tx * 4];
            pr[0] = p0; pr[1] = p1; pr[2] = p2; pr[3] = p3;
        }
        __syncthreads();

        // O += P V
#pragma unroll 8
        for (int c = 0; c < 64; c++) {
            float4 vv = *(const float4*)&Vs[c * 64 + tx * 4];
            float p0 = Ps[(ty * 4 + 0) * 65 + c];
            float p1 = Ps[(ty * 4 + 1) * 65 + c];
            float p2 = Ps[(ty * 4 + 2) * 65 + c];
            float p3 = Ps[(ty * 4 + 3) * 65 + c];
            o[0][0] += p0 * vv.x; o[0][1] += p0 * vv.y; o[0][2] += p0 * vv.z; o[0][3] += p0 * vv.w;
            o[1][0] += p1 * vv.x; o[1][1] += p1 * vv.y; o[1][2] += p1 * vv.z; o[1][3] += p1 * vv.w;
            o[2][0] += p2 * vv.x; o[2][1] += p2 * vv.y; o[2][2] += p2 * vv.z; o[2][3] += p2 * vv.w;
            o[3][0] += p3 * vv.x; o[3][1] += p3 * vv.y; o[3][2] += p3 * vv.z; o[3][3] += p3 * vv.w;
        }
    }

    // Finalize: reduce l across tx, normalize, write [B,S,H*DK]
#pragma unroll
    for (int i = 0; i < 4; i++) {
        float v = li[i];
        v += __shfl_xor_sync(0xffffffffu, v, 1);
        v += __shfl_xor_sync(0xffffffffu, v, 2);
        v += __shfl_xor_sync(0xffffffffu, v, 4);
        v += __shfl_xor_sync(0xffffffffu, v, 8);
        float inv = 1.0f / v;
        float* Op = O + ((size_t)(b * S_) + qt * 64 + ty * 4 + i) * D_ + headoff + tx * 4;
        *(float4*)Op = make_float4(o[i][0] * inv, o[i][1] * inv, o[i][2] * inv, o[i][3] * inv);
    }
}

// ---------------------------------------------------------------------------
// kernel_launch
// ---------------------------------------------------------------------------
extern "C" void kernel_launch(void* const* d_in, const int* in_sizes, int n_in,
                              void* d_out, int out_size)
{
    const float* x  = (const float*)d_in[0];
    const float* wq = (const float*)d_in[1];
    const float* wk = (const float*)d_in[2];
    const float* wv = (const float*)d_in[3];
    const float* wo = (const float*)d_in[4];
    float* out = (float*)d_out;

    float *q, *k, *v, *ao;
    cudaGetSymbolAddress((void**)&q,  g_Q);
    cudaGetSymbolAddress((void**)&k,  g_K);
    cudaGetSymbolAddress((void**)&v,  g_V);
    cudaGetSymbolAddress((void**)&ao, g_AO);

    dim3 ggrid(D_ / 128, M_ / 128);  // (8, 64)
    sgemm_nt<<<ggrid, 256>>>(x, wq, q);
    sgemm_nt<<<ggrid, 256>>>(x, wk, k);
    sgemm_nt<<<ggrid, 256>>>(x, wv, v);

    const size_t smem = (size_t)(3 * 64 * 64 + 64 * 65) * sizeof(float);  // 65792 B
    cudaFuncSetAttribute(attn_kernel, cudaFuncAttributeMaxDynamicSharedMemorySize, (int)smem);
    attn_kernel<<<dim3(S_ / 64, H_, B_), 256, smem>>>(q, k, v, ao);

    sgemm_nt<<<ggrid, 256>>>(ao, wo, out);
}

// round 5
// speedup vs baseline: 1.6856x; 1.6856x over previous
// R5: third submission of the R3 source (R3/R4 were broker-side container
// failures; hang-audit in journal shows this kernel cannot deadlock).
// Testing: bf16x3 mma.sync GEMMs + fp32 flash attn.
#include <cuda_runtime.h>
#include <cuda_bf16.h>
#include <math.h>
#include <stdint.h>

// Problem constants
#define B_  4
#define S_  2048
#define D_  1024
#define H_  16
#define DK_ 64
#define M_  (B_ * S_)   // 8192 rows

// ---------------------------------------------------------------------------
// Scratch (__device__ globals per allocation-free rule)
// ---------------------------------------------------------------------------
__device__ float g_Q [M_ * D_];
__device__ float g_K [M_ * D_];
__device__ float g_V [M_ * D_];
__device__ float g_AO[M_ * D_];
__device__ __nv_bfloat16 g_xhi [M_ * D_];
__device__ __nv_bfloat16 g_xlo [M_ * D_];
__device__ __nv_bfloat16 g_aohi[M_ * D_];
__device__ __nv_bfloat16 g_aolo[M_ * D_];
__device__ __nv_bfloat16 g_whi [4][D_ * D_];
__device__ __nv_bfloat16 g_wlo [4][D_ * D_];

// ---------------------------------------------------------------------------
// PTX helpers: cp.async / ldmatrix / mma.sync (all valid on compute_100)
// ---------------------------------------------------------------------------
__device__ __forceinline__ uint32_t smem_u32(const void* p) {
    uint32_t a;
    asm("{ .reg .u64 t; cvta.to.shared.u64 t, %1; cvt.u32.u64 %0, t; }" : "=r"(a) : "l"(p));
    return a;
}

#define CP_ASYNC_16(sa, gp) \
    asm volatile("cp.async.cg.shared.global [%0], [%1], 16;" :: "r"(sa), "l"(gp))
#define CP_COMMIT() asm volatile("cp.async.commit_group;" ::: "memory")
template<int N> __device__ __forceinline__ void cp_wait() {
    asm volatile("cp.async.wait_group %0;" :: "n"(N) : "memory");
}

// swizzled byte offset inside one 128x32 bf16 tile (64B rows, 16B chunks)
__device__ __forceinline__ uint32_t sw_off(int row, int chunk) {
    return (uint32_t)(row * 64 + ((chunk ^ ((row >> 1) & 3)) << 4));
}

// A-fragment ldmatrix: mats = {(m0,k0),(m8,k0),(m0,k8),(m8,k8)}
__device__ __forceinline__ void ldm_a(uint32_t tile, int row0, int kstep, int lane, uint32_t* r) {
    int row = row0 + (lane & 15);
    int ck  = kstep * 2 + ((lane >> 4) & 1);
    uint32_t addr = tile + sw_off(row, ck);
    asm volatile("ldmatrix.sync.aligned.m8n8.x4.shared.b16 {%0,%1,%2,%3}, [%4];"
                 : "=r"(r[0]), "=r"(r[1]), "=r"(r[2]), "=r"(r[3]) : "r"(addr));
}

// B-fragment ldmatrix: two n-tiles: {(n0,k0),(n0,k8),(n8,k0),(n8,k8)}
__device__ __forceinline__ void ldm_b(uint32_t tile, int row0, int kstep, int lane, uint32_t* r) {
    int row = row0 + (lane & 7) + ((lane & 16) ? 8 : 0);
    int ck  = kstep * 2 + ((lane >> 3) & 1);
    uint32_t addr = tile + sw_off(row, ck);
    asm volatile("ldmatrix.sync.aligned.m8n8.x4.shared.b16 {%0,%1,%2,%3}, [%4];"
                 : "=r"(r[0]), "=r"(r[1]), "=r"(r[2]), "=r"(r[3]) : "r"(addr));
}

__device__ __forceinline__ void mma16816(float* d, const uint32_t* a, const uint32_t* b) {
    asm volatile("mma.sync.aligned.m16n8k16.row.col.f32.bf16.bf16.f32 "
                 "{%0,%1,%2,%3}, {%4,%5,%6,%7}, {%8,%9}, {%0,%1,%2,%3};"
                 : "+f"(d[0]), "+f"(d[1]), "+f"(d[2]), "+f"(d[3])
                 : "r"(a[0]), "r"(a[1]), "r"(a[2]), "r"(a[3]), "r"(b[0]), "r"(b[1]));
}

// ---------------------------------------------------------------------------
// fp32 -> (hi, lo) bf16 split
// ---------------------------------------------------------------------------
__global__ __launch_bounds__(256) void f32_to_hilo(const float* __restrict__ in,
                                                   __nv_bfloat16* __restrict__ hi,
                                                   __nv_bfloat16* __restrict__ lo,
                                                   int n2)
{
    int i = blockIdx.x * blockDim.x + threadIdx.x;
    if (i >= n2) return;
    float2 v = ((const float2*)in)[i];
    __nv_bfloat16 hx = __float2bfloat16_rn(v.x);
    __nv_bfloat16 hy = __float2bfloat16_rn(v.y);
    __nv_bfloat16 lx = __float2bfloat16_rn(v.x - __bfloat162float(hx));
    __nv_bfloat16 ly = __float2bfloat16_rn(v.y - __bfloat162float(hy));
    __nv_bfloat162 h2; h2.x = hx; h2.y = hy;
    __nv_bfloat162 l2; l2.x = lx; l2.y = ly;
    ((__nv_bfloat162*)hi)[i] = h2;
    ((__nv_bfloat162*)lo)[i] = l2;
}

// ---------------------------------------------------------------------------
// bf16x3 GEMM via mma.sync (NT): C[m][n] = sum_k A[m][k] * W[n][k], fp32 accum
// CTA 128x128, BK=32, 8 warps (2m x 4n), warp tile 64x32, double-buffered.
// Smem stage (32KB): Ah@0, Al@8K, Bh@16K, Bl@24K; each 128 rows x 64B swizzled.
// ---------------------------------------------------------------------------
#define STAGE_B   32768
#define GEMM_SMEM (2 * STAGE_B)
#define NCHUNK    32            // K / BK = 1024 / 32

__global__ __launch_bounds__(256) void gemm128_bf16x3(
    const __nv_bfloat16* __restrict__ Ahi, const __nv_bfloat16* __restrict__ Alo,
    const __nv_bfloat16* __restrict__ Bhi, const __nv_bfloat16* __restrict__ Blo,
    float* __restrict__ C)
{
    extern __shared__ __align__(1024) char smem[];
    const uint32_t sb = smem_u32(smem);

    const int t    = threadIdx.x;
    const int lane = t & 31;
    const int w    = t >> 5;
    const int wm   = (w >> 2) * 64;   // 0 or 64
    const int wn   = (w & 3) * 32;    // 0,32,64,96
    const int bm   = blockIdx.y * 128;
    const int bn   = blockIdx.x * 128;

    // load mapping: per matrix, 512 (row,chunk) 16B pieces; 2 per thread
    const int r0 = t >> 2,           c0 = t & 3;         // id = t
    const int r1 = (t + 256) >> 2,   c1 = t & 3;         // id = t + 256

    auto load_chunk = [&](int chunk, int st) {
        const size_t kb = (size_t)chunk * 32;
        const uint32_t s = sb + (uint32_t)st * STAGE_B;
        // piece 0
        {
            uint32_t so = sw_off(r0, c0);
            const size_t ga = (size_t)(bm + r0) * D_ + kb + c0 * 8;
            const size_t gb = (size_t)(bn + r0) * D_ + kb + c0 * 8;
            CP_ASYNC_16(s + so,         Ahi + ga);
            CP_ASYNC_16(s + 8192  + so, Alo + ga);
            CP_ASYNC_16(s + 16384 + so, Bhi + gb);
            CP_ASYNC_16(s + 24576 + so, Blo + gb);
        }
        // piece 1
        {
            uint32_t so = sw_off(r1, c1);
            const size_t ga = (size_t)(bm + r1) * D_ + kb + c1 * 8;
            const size_t gb = (size_t)(bn + r1) * D_ + kb + c1 * 8;
            CP_ASYNC_16(s + so,         Ahi + ga);
            CP_ASYNC_16(s + 8192  + so, Alo + ga);
            CP_ASYNC_16(s + 16384 + so, Bhi + gb);
            CP_ASYNC_16(s + 24576 + so, Blo + gb);
        }
        CP_COMMIT();
    };

    float d[4][4][4];
#pragma unroll
    for (int i = 0; i < 4; i++)
#pragma unroll
        for (int j = 0; j < 4; j++)
#pragma unroll
            for (int e = 0; e < 4; e++) d[i][j][e] = 0.0f;

    load_chunk(0, 0);

    for (int chunk = 0; chunk < NCHUNK; chunk++) {
        const int st = chunk & 1;
        if (chunk + 1 < NCHUNK) { load_chunk(chunk + 1, st ^ 1); cp_wait<1>(); }
        else                    { cp_wait<0>(); }
        __syncthreads();

        const uint32_t tAh = sb + (uint32_t)st * STAGE_B;
        const uint32_t tAl = tAh + 8192;
        const uint32_t tBh = tAh + 16384;
        const uint32_t tBl = tAh + 24576;

#pragma unroll
        for (int ks = 0; ks < 2; ks++) {
            uint32_t ah[4][4], al[4][4];
#pragma unroll
            for (int i = 0; i < 4; i++) {
                ldm_a(tAh, wm + i * 16, ks, lane, ah[i]);
                ldm_a(tAl, wm + i * 16, ks, lane, al[i]);
            }
            uint32_t bh[2][4], bl[2][4];   // [jpair][4 regs = 2 n-tiles x 2]
#pragma unroll
            for (int jp = 0; jp < 2; jp++) {
                ldm_b(tBh, wn + jp * 16, ks, lane, bh[jp]);
                ldm_b(tBl, wn + jp * 16, ks, lane, bl[jp]);
            }
#pragma unroll
            for (int i = 0; i < 4; i++)
#pragma unroll
                for (int j = 0; j < 4; j++) {
                    const uint32_t* ph = &bh[j >> 1][(j & 1) * 2];
                    const uint32_t* pl = &bl[j >> 1][(j & 1) * 2];
                    mma16816(d[i][j], ah[i], ph);
                    mma16816(d[i][j], ah[i], pl);
                    mma16816(d[i][j], al[i], ph);
                }
        }
        __syncthreads();
    }

    // Epilogue: direct STG, float2 per fragment half
#pragma unroll
    for (int i = 0; i < 4; i++) {
        const int row = bm + wm + i * 16 + (lane >> 2);
#pragma unroll
        for (int j = 0; j < 4; j++) {
            const int col = bn + wn + j * 8 + (lane & 3) * 2;
            *(float2*)(C + (size_t)row * D_ + col)       = make_float2(d[i][j][0], d[i][j][1]);
            *(float2*)(C + (size_t)(row + 8) * D_ + col) = make_float2(d[i][j][2], d[i][j][3]);
        }
    }
}

// ---------------------------------------------------------------------------
// Causal flash attention, fp32 (unchanged from round 1 — passed)
// ---------------------------------------------------------------------------
__global__ __launch_bounds__(256) void attn_kernel(const float* __restrict__ Q,
                                                   const float* __restrict__ K,
                                                   const float* __restrict__ V,
                                                   float* __restrict__ O)
{
    extern __shared__ float sm[];
    float* Qs = sm;               // [64][64] d-major
    float* Ks = sm + 4096;        // [64][64] d-major
    float* Vs = sm + 8192;        // [64][64] c-major
    float* Ps = sm + 12288;       // [64][65] r-major

    const int qt = blockIdx.x;
    const int h  = blockIdx.y;
    const int b  = blockIdx.z;
    const int t  = threadIdx.x;
    const int tx = t & 15;
    const int ty = t >> 4;

    const size_t headoff = (size_t)h * DK_;
    const float* Qg = Q + ((size_t)(b * S_) + qt * 64) * D_ + headoff;

#pragma unroll
    for (int idx = t; idx < 1024; idx += 256) {
        int r = idx >> 4, d = (idx & 15) << 2;
        float4 v = *(const float4*)(Qg + (size_t)r * D_ + d);
        Qs[(d + 0) * 64 + r] = v.x * 0.125f;
        Qs[(d + 1) * 64 + r] = v.y * 0.125f;
        Qs[(d + 2) * 64 + r] = v.z * 0.125f;
        Qs[(d + 3) * 64 + r] = v.w * 0.125f;
    }

    float o[4][4];
    float mi[4], li[4];
#pragma unroll
    for (int i = 0; i < 4; i++) {
        mi[i] = -INFINITY; li[i] = 0.0f;
#pragma unroll
        for (int j = 0; j < 4; j++) o[i][j] = 0.0f;
    }

    for (int kt = 0; kt <= qt; kt++) {
        __syncthreads();
        const float* Kg = K + ((size_t)(b * S_) + kt * 64) * D_ + headoff;
        const float* Vg = V + ((size_t)(b * S_) + kt * 64) * D_ + headoff;
#pragma unroll
        for (int idx = t; idx < 1024; idx += 256) {
            int r = idx >> 4, d = (idx & 15) << 2;
            float4 kv = *(const float4*)(Kg + (size_t)r * D_ + d);
            Ks[(d + 0) * 64 + r] = kv.x;
            Ks[(d + 1) * 64 + r] = kv.y;
            Ks[(d + 2) * 64 + r] = kv.z;
            Ks[(d + 3) * 64 + r] = kv.w;
            float4 vv = *(const float4*)(Vg + (size_t)r * D_ + d);
            *(float4*)&Vs[r * 64 + d] = vv;
        }
        __syncthreads();

        float s[4][4];
#pragma unroll
        for (int i = 0; i < 4; i++)
#pragma unroll
            for (int j = 0; j < 4; j++) s[i][j] = 0.0f;

#pragma unroll 8
        for (int dd = 0; dd < 64; dd++) {
            float4 qv = *(const float4*)&Qs[dd * 64 + ty * 4];
            float4 kv = *(const float4*)&Ks[dd * 64 + tx * 4];
            float qa[4] = {qv.x, qv.y, qv.z, qv.w};
            float ka[4] = {kv.x, kv.y, kv.z, kv.w};
#pragma unroll
            for (int i = 0; i < 4; i++)
#pragma unroll
                for (int j = 0; j < 4; j++) s[i][j] += qa[i] * ka[j];
        }

        if (kt == qt) {
#pragma unroll
            for (int i = 0; i < 4; i++)
#pragma unroll
                for (int j = 0; j < 4; j++)
                    if (tx * 4 + j > ty * 4 + i) s[i][j] = -INFINITY;
        }

#pragma unroll
        for (int i = 0; i < 4; i++) {
            float v = fmaxf(fmaxf(s[i][0], s[i][1]), fmaxf(s[i][2], s[i][3]));
            v = fmaxf(v, __shfl_xor_sync(0xffffffffu, v, 1));
            v = fmaxf(v, __shfl_xor_sync(0xffffffffu, v, 2));
            v = fmaxf(v, __shfl_xor_sync(0xffffffffu, v, 4));
            v = fmaxf(v, __shfl_xor_sync(0xffffffffu, v, 8));
            float mn    = fmaxf(mi[i], v);
            float alpha = __expf(mi[i] - mn);
            mi[i] = mn;
            li[i] *= alpha;
            o[i][0] *= alpha; o[i][1] *= alpha; o[i][2] *= alpha; o[i][3] *= alpha;
            float p0 = __expf(s[i][0] - mn);
            float p1 = __expf(s[i][1] - mn);
            float p2 = __expf(s[i][2] - mn);
            float p3 = __expf(s[i][3] - mn);
            li[i] += (p0 + p1) + (p2 + p3);
            float* pr = &Ps[(ty * 4 + i) * 65 + tx * 4];
            pr[0] = p0; pr[1] = p1; pr[2] = p2; pr[3] = p3;
        }
        __syncthreads();

#pragma unroll 8
        for (int c = 0; c < 64; c++) {
            float4 vv = *(const float4*)&Vs[c * 64 + tx * 4];
            float p0 = Ps[(ty * 4 + 0) * 65 + c];
            float p1 = Ps[(ty * 4 + 1) * 65 + c];
            float p2 = Ps[(ty * 4 + 2) * 65 + c];
            float p3 = Ps[(ty * 4 + 3) * 65 + c];
            o[0][0] += p0 * vv.x; o[0][1] += p0 * vv.y; o[0][2] += p0 * vv.z; o[0][3] += p0 * vv.w;
            o[1][0] += p1 * vv.x; o[1][1] += p1 * vv.y; o[1][2] += p1 * vv.z; o[1][3] += p1 * vv.w;
            o[2][0] += p2 * vv.x; o[2][1] += p2 * vv.y; o[2][2] += p2 * vv.z; o[2][3] += p2 * vv.w;
            o[3][0] += p3 * vv.x; o[3][1] += p3 * vv.y; o[3][2] += p3 * vv.z; o[3][3] += p3 * vv.w;
        }
    }

#pragma unroll
    for (int i = 0; i < 4; i++) {
        float v = li[i];
        v += __shfl_xor_sync(0xffffffffu, v, 1);
        v += __shfl_xor_sync(0xffffffffu, v, 2);
        v += __shfl_xor_sync(0xffffffffu, v, 4);
        v += __shfl_xor_sync(0xffffffffu, v, 8);
        float inv = 1.0f / v;
        float* Op = O + ((size_t)(b * S_) + qt * 64 + ty * 4 + i) * D_ + headoff + tx * 4;
        *(float4*)Op = make_float4(o[i][0] * inv, o[i][1] * inv, o[i][2] * inv, o[i][3] * inv);
    }
}

// ---------------------------------------------------------------------------
// kernel_launch
// ---------------------------------------------------------------------------
extern "C" void kernel_launch(void* const* d_in, const int* in_sizes, int n_in,
                              void* d_out, int out_size)
{
    const float* x  = (const float*)d_in[0];
    const float* w[4] = { (const float*)d_in[1], (const float*)d_in[2],
                          (const float*)d_in[3], (const float*)d_in[4] };
    float* out = (float*)d_out;

    float *q, *k, *v, *ao;
    __nv_bfloat16 *xhi, *xlo, *aohi, *aolo, *whi, *wlo;
    cudaGetSymbolAddress((void**)&q,    g_Q);
    cudaGetSymbolAddress((void**)&k,    g_K);
    cudaGetSymbolAddress((void**)&v,    g_V);
    cudaGetSymbolAddress((void**)&ao,   g_AO);
    cudaGetSymbolAddress((void**)&xhi,  g_xhi);
    cudaGetSymbolAddress((void**)&xlo,  g_xlo);
    cudaGetSymbolAddress((void**)&aohi, g_aohi);
    cudaGetSymbolAddress((void**)&aolo, g_aolo);
    cudaGetSymbolAddress((void**)&whi,  g_whi);
    cudaGetSymbolAddress((void**)&wlo,  g_wlo);

    const int n2x = M_ * D_ / 2;
    const int n2w = D_ * D_ / 2;
    f32_to_hilo<<<(n2x + 255) / 256, 256>>>(x, xhi, xlo, n2x);
    for (int i = 0; i < 4; i++)
        f32_to_hilo<<<(n2w + 255) / 256, 256>>>(w[i], whi + (size_t)i * D_ * D_,
                                                wlo + (size_t)i * D_ * D_, n2w);

    cudaFuncSetAttribute(gemm128_bf16x3, cudaFuncAttributeMaxDynamicSharedMemorySize, GEMM_SMEM);
    dim3 gg(D_ / 128, M_ / 128);  // (8, 64)
    gemm128_bf16x3<<<gg, 256, GEMM_SMEM>>>(xhi, xlo, whi + 0 * (size_t)(D_ * D_), wlo + 0 * (size_t)(D_ * D_), q);
    gemm128_bf16x3<<<gg, 256, GEMM_SMEM>>>(xhi, xlo, whi + 1 * (size_t)(D_ * D_), wlo + 1 * (size_t)(D_ * D_), k);
    gemm128_bf16x3<<<gg, 256, GEMM_SMEM>>>(xhi, xlo, whi + 2 * (size_t)(D_ * D_), wlo + 2 * (size_t)(D_ * D_), v);

    const size_t asmem = (size_t)(3 * 64 * 64 + 64 * 65) * sizeof(float);  // 65792 B
    cudaFuncSetAttribute(attn_kernel, cudaFuncAttributeMaxDynamicSharedMemorySize, (int)asmem);
    attn_kernel<<<dim3(S_ / 64, H_, B_), 256, asmem>>>(q, k, v, ao);

    f32_to_hilo<<<(n2x + 255) / 256, 256>>>(ao, aohi, aolo, n2x);
    gemm128_bf16x3<<<gg, 256, GEMM_SMEM>>>(aohi, aolo, whi + 3 * (size_t)(D_ * D_), wlo + 3 * (size_t)(D_ * D_), out);
}

// round 6
// speedup vs baseline: 3.5688x; 2.1173x over previous
// R6: attention onto validated bf16x3 mma.sync fragments; GEMM epilogues emit
// hi/lo bf16 (Q scaled by 0.125); P reused from S fragments, V via ldmatrix.trans.
#include <cuda_runtime.h>
#include <cuda_bf16.h>
#include <math.h>
#include <stdint.h>

#define B_  4
#define S_  2048
#define D_  1024
#define H_  16
#define DK_ 64
#define M_  (B_ * S_)

// ---------------------------------------------------------------------------
// Scratch
// ---------------------------------------------------------------------------
__device__ __nv_bfloat16 g_xhi [M_ * D_];
__device__ __nv_bfloat16 g_xlo [M_ * D_];
__device__ __nv_bfloat16 g_qhi [M_ * D_];
__device__ __nv_bfloat16 g_qlo [M_ * D_];
__device__ __nv_bfloat16 g_khi [M_ * D_];
__device__ __nv_bfloat16 g_klo [M_ * D_];
__device__ __nv_bfloat16 g_vhi [M_ * D_];
__device__ __nv_bfloat16 g_vlo [M_ * D_];
__device__ __nv_bfloat16 g_aohi[M_ * D_];
__device__ __nv_bfloat16 g_aolo[M_ * D_];
__device__ __nv_bfloat16 g_whi [4][D_ * D_];
__device__ __nv_bfloat16 g_wlo [4][D_ * D_];

// ---------------------------------------------------------------------------
// PTX helpers
// ---------------------------------------------------------------------------
__device__ __forceinline__ uint32_t smem_u32(const void* p) {
    uint32_t a;
    asm("{ .reg .u64 t; cvta.to.shared.u64 t, %1; cvt.u32.u64 %0, t; }" : "=r"(a) : "l"(p));
    return a;
}

#define CP_ASYNC_16(sa, gp) \
    asm volatile("cp.async.cg.shared.global [%0], [%1], 16;" :: "r"(sa), "l"(gp))
#define CP_COMMIT() asm volatile("cp.async.commit_group;" ::: "memory")
template<int N> __device__ __forceinline__ void cp_wait() {
    asm volatile("cp.async.wait_group %0;" :: "n"(N) : "memory");
}

__device__ __forceinline__ void mma16816(float* d, const uint32_t* a, const uint32_t* b) {
    asm volatile("mma.sync.aligned.m16n8k16.row.col.f32.bf16.bf16.f32 "
                 "{%0,%1,%2,%3}, {%4,%5,%6,%7}, {%8,%9}, {%0,%1,%2,%3};"
                 : "+f"(d[0]), "+f"(d[1]), "+f"(d[2]), "+f"(d[3])
                 : "r"(a[0]), "r"(a[1]), "r"(a[2]), "r"(a[3]), "r"(b[0]), "r"(b[1]));
}

// fp32 pair -> bf16x2 hi + exact residual bf16x2 lo. a = even col, b = odd col.
__device__ __forceinline__ void pack_hilo(float a, float b, uint32_t& hi, uint32_t& lo) {
    uint32_t h;
    asm("cvt.rn.bf16x2.f32 %0, %1, %2;" : "=r"(h) : "f"(b), "f"(a));
    float ra = a - __uint_as_float(h << 16);
    float rb = b - __uint_as_float(h & 0xffff0000u);
    uint32_t l;
    asm("cvt.rn.bf16x2.f32 %0, %1, %2;" : "=r"(l) : "f"(rb), "f"(ra));
    hi = h; lo = l;
}

// ----- 64B-row tiles (GEMM, BK=32) -----
__device__ __forceinline__ uint32_t sw_off(int row, int chunk) {
    return (uint32_t)(row * 64 + ((chunk ^ ((row >> 1) & 3)) << 4));
}
__device__ __forceinline__ void ldm_a(uint32_t tile, int row0, int kstep, int lane, uint32_t* r) {
    int row = row0 + (lane & 15);
    int ck  = kstep * 2 + ((lane >> 4) & 1);
    uint32_t addr = tile + sw_off(row, ck);
    asm volatile("ldmatrix.sync.aligned.m8n8.x4.shared.b16 {%0,%1,%2,%3}, [%4];"
                 : "=r"(r[0]), "=r"(r[1]), "=r"(r[2]), "=r"(r[3]) : "r"(addr));
}
__device__ __forceinline__ void ldm_b(uint32_t tile, int row0, int kstep, int lane, uint32_t* r) {
    int row = row0 + (lane & 7) + ((lane & 16) ? 8 : 0);
    int ck  = kstep * 2 + ((lane >> 3) & 1);
    uint32_t addr = tile + sw_off(row, ck);
    asm volatile("ldmatrix.sync.aligned.m8n8.x4.shared.b16 {%0,%1,%2,%3}, [%4];"
                 : "=r"(r[0]), "=r"(r[1]), "=r"(r[2]), "=r"(r[3]) : "r"(addr));
}

// ----- 128B-row tiles (attention, 64x64 bf16) -----
__device__ __forceinline__ uint32_t swoff128(int row, int ck) {
    return (uint32_t)(row * 128 + ((ck ^ (row & 7)) << 4));
}
__device__ __forceinline__ void ldm_a128(uint32_t tile, int row0, int t4, int lane, uint32_t* r) {
    int row = row0 + (lane & 15);
    int ck  = t4 * 2 + ((lane >> 4) & 1);
    uint32_t addr = tile + swoff128(row, ck);
    asm volatile("ldmatrix.sync.aligned.m8n8.x4.shared.b16 {%0,%1,%2,%3}, [%4];"
                 : "=r"(r[0]), "=r"(r[1]), "=r"(r[2]), "=r"(r[3]) : "r"(addr));
}
__device__ __forceinline__ void ldm_b128(uint32_t tile, int n0, int t4, int lane, uint32_t* r) {
    int row = n0 + (lane & 7) + ((lane >> 1) & 8);
    int ck  = t4 * 2 + ((lane >> 3) & 1);
    uint32_t addr = tile + swoff128(row, ck);
    asm volatile("ldmatrix.sync.aligned.m8n8.x4.shared.b16 {%0,%1,%2,%3}, [%4];"
                 : "=r"(r[0]), "=r"(r[1]), "=r"(r[2]), "=r"(r[3]) : "r"(addr));
}
// V^T fragments from V stored [key][d]: mats {(n0,k0),(n0,k8),(n8... )} via trans
__device__ __forceinline__ void ldm_vt128(uint32_t tile, int k0, int jp, int lane, uint32_t* r) {
    int row = k0 + (lane & 7) + (lane & 8);
    int ck  = jp * 2 + ((lane >> 4) & 1);
    uint32_t addr = tile + swoff128(row, ck);
    asm volatile("ldmatrix.sync.aligned.m8n8.x4.trans.shared.b16 {%0,%1,%2,%3}, [%4];"
                 : "=r"(r[0]), "=r"(r[1]), "=r"(r[2]), "=r"(r[3]) : "r"(addr));
}

// ---------------------------------------------------------------------------
// fp32 -> (hi, lo) bf16 split (x and weights)
// ---------------------------------------------------------------------------
__global__ __launch_bounds__(256) void f32_to_hilo(const float* __restrict__ in,
                                                   __nv_bfloat16* __restrict__ hi,
                                                   __nv_bfloat16* __restrict__ lo,
                                                   int n2)
{
    int i = blockIdx.x * blockDim.x + threadIdx.x;
    if (i >= n2) return;
    float2 v = ((const float2*)in)[i];
    uint32_t h, l;
    pack_hilo(v.x, v.y, h, l);
    ((uint32_t*)hi)[i] = h;
    ((uint32_t*)lo)[i] = l;
}

// ---------------------------------------------------------------------------
// bf16x3 GEMM (NT), templated epilogue:
//   EPI=0: fp32 C.   EPI=1: bf16 hi/lo (C*scale split), for Q/K/V.
// ---------------------------------------------------------------------------
#define STAGE_B   32768
#define GEMM_SMEM (2 * STAGE_B)
#define NCHUNK    32

template<int EPI>
__global__ __launch_bounds__(256) void gemm128_bf16x3(
    const __nv_bfloat16* __restrict__ Ahi, const __nv_bfloat16* __restrict__ Alo,
    const __nv_bfloat16* __restrict__ Bhi, const __nv_bfloat16* __restrict__ Blo,
    float* __restrict__ C,
    __nv_bfloat16* __restrict__ Chi, __nv_bfloat16* __restrict__ Clo, float scale)
{
    extern __shared__ __align__(1024) char smem[];
    const uint32_t sb = smem_u32(smem);

    const int t    = threadIdx.x;
    const int lane = t & 31;
    const int w    = t >> 5;
    const int wm   = (w >> 2) * 64;
    const int wn   = (w & 3) * 32;
    const int bm   = blockIdx.y * 128;
    const int bn   = blockIdx.x * 128;

    const int r0 = t >> 2,         c0 = t & 3;
    const int r1 = (t + 256) >> 2, c1 = t & 3;

    auto load_chunk = [&](int chunk, int st) {
        const size_t kb = (size_t)chunk * 32;
        const uint32_t s = sb + (uint32_t)st * STAGE_B;
        {
            uint32_t so = sw_off(r0, c0);
            const size_t ga = (size_t)(bm + r0) * D_ + kb + c0 * 8;
            const size_t gb = (size_t)(bn + r0) * D_ + kb + c0 * 8;
            CP_ASYNC_16(s + so,         Ahi + ga);
            CP_ASYNC_16(s + 8192  + so, Alo + ga);
            CP_ASYNC_16(s + 16384 + so, Bhi + gb);
            CP_ASYNC_16(s + 24576 + so, Blo + gb);
        }
        {
            uint32_t so = sw_off(r1, c1);
            const size_t ga = (size_t)(bm + r1) * D_ + kb + c1 * 8;
            const size_t gb = (size_t)(bn + r1) * D_ + kb + c1 * 8;
            CP_ASYNC_16(s + so,         Ahi + ga);
            CP_ASYNC_16(s + 8192  + so, Alo + ga);
            CP_ASYNC_16(s + 16384 + so, Bhi + gb);
            CP_ASYNC_16(s + 24576 + so, Blo + gb);
        }
        CP_COMMIT();
    };

    float d[4][4][4];
#pragma unroll
    for (int i = 0; i < 4; i++)
#pragma unroll
        for (int j = 0; j < 4; j++)
#pragma unroll
            for (int e = 0; e < 4; e++) d[i][j][e] = 0.0f;

    load_chunk(0, 0);

    for (int chunk = 0; chunk < NCHUNK; chunk++) {
        const int st = chunk & 1;
        if (chunk + 1 < NCHUNK) { load_chunk(chunk + 1, st ^ 1); cp_wait<1>(); }
        else                    { cp_wait<0>(); }
        __syncthreads();

        const uint32_t tAh = sb + (uint32_t)st * STAGE_B;
        const uint32_t tAl = tAh + 8192;
        const uint32_t tBh = tAh + 16384;
        const uint32_t tBl = tAh + 24576;

#pragma unroll
        for (int ks = 0; ks < 2; ks++) {
            uint32_t ah[4][4], al[4][4];
#pragma unroll
            for (int i = 0; i < 4; i++) {
                ldm_a(tAh, wm + i * 16, ks, lane, ah[i]);
                ldm_a(tAl, wm + i * 16, ks, lane, al[i]);
            }
            uint32_t bh[2][4], bl[2][4];
#pragma unroll
            for (int jp = 0; jp < 2; jp++) {
                ldm_b(tBh, wn + jp * 16, ks, lane, bh[jp]);
                ldm_b(tBl, wn + jp * 16, ks, lane, bl[jp]);
            }
#pragma unroll
            for (int i = 0; i < 4; i++)
#pragma unroll
                for (int j = 0; j < 4; j++) {
                    const uint32_t* ph = &bh[j >> 1][(j & 1) * 2];
                    const uint32_t* pl = &bl[j >> 1][(j & 1) * 2];
                    mma16816(d[i][j], ah[i], ph);
                    mma16816(d[i][j], ah[i], pl);
                    mma16816(d[i][j], al[i], ph);
                }
        }
        __syncthreads();
    }

#pragma unroll
    for (int i = 0; i < 4; i++) {
        const int row = bm + wm + i * 16 + (lane >> 2);
#pragma unroll
        for (int j = 0; j < 4; j++) {
            const int col = bn + wn + j * 8 + (lane & 3) * 2;
            if (EPI == 0) {
                *(float2*)(C + (size_t)row * D_ + col)       = make_float2(d[i][j][0], d[i][j][1]);
                *(float2*)(C + (size_t)(row + 8) * D_ + col) = make_float2(d[i][j][2], d[i][j][3]);
            } else {
                uint32_t h01, l01, h23, l23;
                pack_hilo(d[i][j][0] * scale, d[i][j][1] * scale, h01, l01);
                pack_hilo(d[i][j][2] * scale, d[i][j][3] * scale, h23, l23);
                *(uint32_t*)(Chi + (size_t)row * D_ + col)       = h01;
                *(uint32_t*)(Clo + (size_t)row * D_ + col)       = l01;
                *(uint32_t*)(Chi + (size_t)(row + 8) * D_ + col) = h23;
                *(uint32_t*)(Clo + (size_t)(row + 8) * D_ + col) = l23;
            }
        }
    }
}

// ---------------------------------------------------------------------------
// Flash attention on mma.sync. CTA = (qtile 64 rows, h, b), 128 threads.
// Warp w owns q rows w*16..+15. Smem: Qhi/Qlo + 2 stages of {Khi,Klo,Vhi,Vlo}.
// ---------------------------------------------------------------------------
#define ATT_SMEM 81920

__global__ __launch_bounds__(128) void attn_mma(
    const __nv_bfloat16* __restrict__ Qhi, const __nv_bfloat16* __restrict__ Qlo,
    const __nv_bfloat16* __restrict__ Khi, const __nv_bfloat16* __restrict__ Klo,
    const __nv_bfloat16* __restrict__ Vhi, const __nv_bfloat16* __restrict__ Vlo,
    __nv_bfloat16* __restrict__ AOhi, __nv_bfloat16* __restrict__ AOlo)
{
    extern __shared__ __align__(1024) char smem[];
    const uint32_t sb = smem_u32(smem);
    const int qt   = (int)gridDim.x - 1 - (int)blockIdx.x;  // largest tiles first
    const int h    = blockIdx.y;
    const int b    = blockIdx.z;
    const int tid  = threadIdx.x;
    const int lane = tid & 31;
    const int w    = tid >> 5;

    const size_t rowbase = (size_t)b * S_;
    const size_t cb      = (size_t)h * DK_;
    const int    q0      = qt * 64;

    const uint32_t sQh = sb, sQl = sb + 8192;

    // prologue: Q tiles
#pragma unroll
    for (int i = 0; i < 4; i++) {
        int p = tid + 128 * i; int r = p >> 3, ck = p & 7;
        size_t g = (rowbase + q0 + r) * D_ + cb + ck * 8;
        uint32_t so = swoff128(r, ck);
        CP_ASYNC_16(sQh + so, Qhi + g);
        CP_ASYNC_16(sQl + so, Qlo + g);
    }
    CP_COMMIT();

    auto load_kv = [&](int kt, int st) {
        uint32_t s = sb + 16384 + (uint32_t)st * 32768;
#pragma unroll
        for (int i = 0; i < 4; i++) {
            int p = tid + 128 * i; int r = p >> 3, ck = p & 7;
            uint32_t so = swoff128(r, ck);
            size_t g = (rowbase + kt * 64 + r) * D_ + cb + ck * 8;
            CP_ASYNC_16(s + so,         Khi + g);
            CP_ASYNC_16(s + 8192  + so, Klo + g);
            CP_ASYNC_16(s + 16384 + so, Vhi + g);
            CP_ASYNC_16(s + 24576 + so, Vlo + g);
        }
        CP_COMMIT();
    };
    load_kv(0, 0);

    cp_wait<1>();          // Q group done (kv0 may be in flight)
    __syncthreads();

    uint32_t qh[4][4], ql[4][4];
#pragma unroll
    for (int t4 = 0; t4 < 4; t4++) {
        ldm_a128(sQh, w * 16, t4, lane, qh[t4]);
        ldm_a128(sQl, w * 16, t4, lane, ql[t4]);
    }

    float o[8][4];
#pragma unroll
    for (int j = 0; j < 8; j++)
#pragma unroll
        for (int e = 0; e < 4; e++) o[j][e] = 0.0f;
    float miA = -INFINITY, miB = -INFINITY, liA = 0.0f, liB = 0.0f;

    const int rA = w * 16 + (lane >> 2);   // local row (A); B = rA + 8
    const int cl = 2 * (lane & 3);         // local col offset within n-tile

    for (int kt = 0; kt <= qt; kt++) {
        const int st = kt & 1;
        if (kt < qt) { load_kv(kt + 1, st ^ 1); cp_wait<1>(); }
        else         { cp_wait<0>(); }
        __syncthreads();

        const uint32_t Kh = sb + 16384 + (uint32_t)st * 32768;
        const uint32_t Kl = Kh + 8192, Vh = Kh + 16384, Vl = Kh + 24576;

        // S = Q K^T  (bf16x3)
        float s[8][4];
#pragma unroll
        for (int j = 0; j < 8; j++)
#pragma unroll
            for (int e = 0; e < 4; e++) s[j][e] = 0.0f;

#pragma unroll
        for (int t4 = 0; t4 < 4; t4++) {
#pragma unroll
            for (int jp = 0; jp < 4; jp++) {
                uint32_t kh[4], kl[4];
                ldm_b128(Kh, jp * 16, t4, lane, kh);
                ldm_b128(Kl, jp * 16, t4, lane, kl);
                mma16816(s[2 * jp],     qh[t4], kh);
                mma16816(s[2 * jp],     qh[t4], kl);
                mma16816(s[2 * jp],     ql[t4], kh);
                mma16816(s[2 * jp + 1], qh[t4], kh + 2);
                mma16816(s[2 * jp + 1], qh[t4], kl + 2);
                mma16816(s[2 * jp + 1], ql[t4], kh + 2);
            }
        }

        // causal mask (diagonal tile only)
        if (kt == qt) {
#pragma unroll
            for (int j = 0; j < 8; j++) {
                int c = 8 * j + cl;
                if (c     > rA)     s[j][0] = -INFINITY;
                if (c + 1 > rA)     s[j][1] = -INFINITY;
                if (c     > rA + 8) s[j][2] = -INFINITY;
                if (c + 1 > rA + 8) s[j][3] = -INFINITY;
            }
        }

        // online softmax
        float mxA = s[0][0], mxB = s[0][2];
#pragma unroll
        for (int j = 0; j < 8; j++) {
            mxA = fmaxf(mxA, fmaxf(s[j][0], s[j][1]));
            mxB = fmaxf(mxB, fmaxf(s[j][2], s[j][3]));
        }
        mxA = fmaxf(mxA, __shfl_xor_sync(0xffffffffu, mxA, 1));
        mxA = fmaxf(mxA, __shfl_xor_sync(0xffffffffu, mxA, 2));
        mxB = fmaxf(mxB, __shfl_xor_sync(0xffffffffu, mxB, 1));
        mxB = fmaxf(mxB, __shfl_xor_sync(0xffffffffu, mxB, 2));

        float nA = fmaxf(miA, mxA), nB = fmaxf(miB, mxB);
        float aA = __expf(miA - nA), aB = __expf(miB - nB);
        miA = nA; miB = nB;
        liA *= aA; liB *= aB;
#pragma unroll
        for (int j = 0; j < 8; j++) {
            s[j][0] = __expf(s[j][0] - miA);
            s[j][1] = __expf(s[j][1] - miA);
            s[j][2] = __expf(s[j][2] - miB);
            s[j][3] = __expf(s[j][3] - miB);
            liA += s[j][0] + s[j][1];
            liB += s[j][2] + s[j][3];
            o[j][0] *= aA; o[j][1] *= aA; o[j][2] *= aB; o[j][3] *= aB;
        }

        // P fragments (hi/lo) built in-register from S (C-frag == A-frag layout)
        uint32_t ph[4][4], pl[4][4];
#pragma unroll
        for (int t4 = 0; t4 < 4; t4++) {
            pack_hilo(s[2 * t4][0],     s[2 * t4][1],     ph[t4][0], pl[t4][0]);
            pack_hilo(s[2 * t4][2],     s[2 * t4][3],     ph[t4][1], pl[t4][1]);
            pack_hilo(s[2 * t4 + 1][0], s[2 * t4 + 1][1], ph[t4][2], pl[t4][2]);
            pack_hilo(s[2 * t4 + 1][2], s[2 * t4 + 1][3], ph[t4][3], pl[t4][3]);
        }

        // O += P V  (bf16x3; V^T frags via ldmatrix.trans)
#pragma unroll
        for (int t4 = 0; t4 < 4; t4++) {
#pragma unroll
            for (int jp = 0; jp < 4; jp++) {
                uint32_t vh[4], vl[4];
                ldm_vt128(Vh, t4 * 16, jp, lane, vh);
                ldm_vt128(Vl, t4 * 16, jp, lane, vl);
                mma16816(o[2 * jp],     ph[t4], vh);
                mma16816(o[2 * jp],     pl[t4], vh);
                mma16816(o[2 * jp],     ph[t4], vl);
                mma16816(o[2 * jp + 1], ph[t4], vh + 2);
                mma16816(o[2 * jp + 1], pl[t4], vh + 2);
                mma16816(o[2 * jp + 1], ph[t4], vl + 2);
            }
        }
        __syncthreads();   // stage fully consumed before it is refilled
    }

    // epilogue: reduce l across the 4-lane row group, normalize, emit hi/lo bf16
    liA += __shfl_xor_sync(0xffffffffu, liA, 1);
    liA += __shfl_xor_sync(0xffffffffu, liA, 2);
    liB += __shfl_xor_sync(0xffffffffu, liB, 1);
    liB += __shfl_xor_sync(0xffffffffu, liB, 2);
    const float invA = 1.0f / liA, invB = 1.0f / liB;

    const size_t gA = (rowbase + q0 + rA) * D_ + cb + cl;
#pragma unroll
    for (int j = 0; j < 8; j++) {
        uint32_t hA, lA, hB, lB;
        pack_hilo(o[j][0] * invA, o[j][1] * invA, hA, lA);
        pack_hilo(o[j][2] * invB, o[j][3] * invB, hB, lB);
        *(uint32_t*)(AOhi + gA + 8 * j)           = hA;
        *(uint32_t*)(AOlo + gA + 8 * j)           = lA;
        *(uint32_t*)(AOhi + gA + 8 * j + 8 * D_)  = hB;
        *(uint32_t*)(AOlo + gA + 8 * j + 8 * D_)  = lB;
    }
}

// ---------------------------------------------------------------------------
// kernel_launch
// ---------------------------------------------------------------------------
extern "C" void kernel_launch(void* const* d_in, const int* in_sizes, int n_in,
                              void* d_out, int out_size)
{
    const float* x  = (const float*)d_in[0];
    const float* wp[4] = { (const float*)d_in[1], (const float*)d_in[2],
                           (const float*)d_in[3], (const float*)d_in[4] };
    float* out = (float*)d_out;

    __nv_bfloat16 *xhi, *xlo, *qhi, *qlo, *khi, *klo, *vhi, *vlo, *aohi, *aolo, *whi, *wlo;
    cudaGetSymbolAddress((void**)&xhi,  g_xhi);
    cudaGetSymbolAddress((void**)&xlo,  g_xlo);
    cudaGetSymbolAddress((void**)&qhi,  g_qhi);
    cudaGetSymbolAddress((void**)&qlo,  g_qlo);
    cudaGetSymbolAddress((void**)&khi,  g_khi);
    cudaGetSymbolAddress((void**)&klo,  g_klo);
    cudaGetSymbolAddress((void**)&vhi,  g_vhi);
    cudaGetSymbolAddress((void**)&vlo,  g_vlo);
    cudaGetSymbolAddress((void**)&aohi, g_aohi);
    cudaGetSymbolAddress((void**)&aolo, g_aolo);
    cudaGetSymbolAddress((void**)&whi,  g_whi);
    cudaGetSymbolAddress((void**)&wlo,  g_wlo);

    const int n2x = M_ * D_ / 2;
    const int n2w = D_ * D_ / 2;
    f32_to_hilo<<<(n2x + 255) / 256, 256>>>(x, xhi, xlo, n2x);
    for (int i = 0; i < 4; i++)
        f32_to_hilo<<<(n2w + 255) / 256, 256>>>(wp[i], whi + (size_t)i * D_ * D_,
                                                wlo + (size_t)i * D_ * D_, n2w);

    cudaFuncSetAttribute(gemm128_bf16x3<0>, cudaFuncAttributeMaxDynamicSharedMemorySize, GEMM_SMEM);
    cudaFuncSetAttribute(gemm128_bf16x3<1>, cudaFuncAttributeMaxDynamicSharedMemorySize, GEMM_SMEM);
    cudaFuncSetAttribute(attn_mma, cudaFuncAttributeMaxDynamicSharedMemorySize, ATT_SMEM);

    dim3 gg(D_ / 128, M_ / 128);
    gemm128_bf16x3<1><<<gg, 256, GEMM_SMEM>>>(xhi, xlo, whi + 0 * (size_t)(D_ * D_), wlo + 0 * (size_t)(D_ * D_),
                                              nullptr, qhi, qlo, 0.125f);
    gemm128_bf16x3<1><<<gg, 256, GEMM_SMEM>>>(xhi, xlo, whi + 1 * (size_t)(D_ * D_), wlo + 1 * (size_t)(D_ * D_),
                                              nullptr, khi, klo, 1.0f);
    gemm128_bf16x3<1><<<gg, 256, GEMM_SMEM>>>(xhi, xlo, whi + 2 * (size_t)(D_ * D_), wlo + 2 * (size_t)(D_ * D_),
                                              nullptr, vhi, vlo, 1.0f);

    attn_mma<<<dim3(S_ / 64, H_, B_), 128, ATT_SMEM>>>(qhi, qlo, khi, klo, vhi, vlo, aohi, aolo);

    gemm128_bf16x3<0><<<gg, 256, GEMM_SMEM>>>(aohi, aolo, whi + 3 * (size_t)(D_ * D_), wlo + 3 * (size_t)(D_ * D_),
                                              out, nullptr, nullptr, 1.0f);
}

// round 7
// speedup vs baseline: 3.7056x; 1.0383x over previous
// R7: fuse Q/K/V projections into ONE kernel (grid.x = 3 weights x 8 n-tiles)
// to fix 1.73-wave quantization and reuse A-tiles in L2. Attention unchanged.
#include <cuda_runtime.h>
#include <cuda_bf16.h>
#include <math.h>
#include <stdint.h>

#define B_  4
#define S_  2048
#define D_  1024
#define H_  16
#define DK_ 64
#define M_  (B_ * S_)

// ---------------------------------------------------------------------------
// Scratch
// ---------------------------------------------------------------------------
__device__ __nv_bfloat16 g_xhi [M_ * D_];
__device__ __nv_bfloat16 g_xlo [M_ * D_];
__device__ __nv_bfloat16 g_qhi [M_ * D_];
__device__ __nv_bfloat16 g_qlo [M_ * D_];
__device__ __nv_bfloat16 g_khi [M_ * D_];
__device__ __nv_bfloat16 g_klo [M_ * D_];
__device__ __nv_bfloat16 g_vhi [M_ * D_];
__device__ __nv_bfloat16 g_vlo [M_ * D_];
__device__ __nv_bfloat16 g_aohi[M_ * D_];
__device__ __nv_bfloat16 g_aolo[M_ * D_];
__device__ __nv_bfloat16 g_whi [4][D_ * D_];
__device__ __nv_bfloat16 g_wlo [4][D_ * D_];

// ---------------------------------------------------------------------------
// PTX helpers
// ---------------------------------------------------------------------------
__device__ __forceinline__ uint32_t smem_u32(const void* p) {
    uint32_t a;
    asm("{ .reg .u64 t; cvta.to.shared.u64 t, %1; cvt.u32.u64 %0, t; }" : "=r"(a) : "l"(p));
    return a;
}

#define CP_ASYNC_16(sa, gp) \
    asm volatile("cp.async.cg.shared.global [%0], [%1], 16;" :: "r"(sa), "l"(gp))
#define CP_COMMIT() asm volatile("cp.async.commit_group;" ::: "memory")
template<int N> __device__ __forceinline__ void cp_wait() {
    asm volatile("cp.async.wait_group %0;" :: "n"(N) : "memory");
}

__device__ __forceinline__ void mma16816(float* d, const uint32_t* a, const uint32_t* b) {
    asm volatile("mma.sync.aligned.m16n8k16.row.col.f32.bf16.bf16.f32 "
                 "{%0,%1,%2,%3}, {%4,%5,%6,%7}, {%8,%9}, {%0,%1,%2,%3};"
                 : "+f"(d[0]), "+f"(d[1]), "+f"(d[2]), "+f"(d[3])
                 : "r"(a[0]), "r"(a[1]), "r"(a[2]), "r"(a[3]), "r"(b[0]), "r"(b[1]));
}

// fp32 pair -> bf16x2 hi + exact residual bf16x2 lo. a = even col, b = odd col.
__device__ __forceinline__ void pack_hilo(float a, float b, uint32_t& hi, uint32_t& lo) {
    uint32_t h;
    asm("cvt.rn.bf16x2.f32 %0, %1, %2;" : "=r"(h) : "f"(b), "f"(a));
    float ra = a - __uint_as_float(h << 16);
    float rb = b - __uint_as_float(h & 0xffff0000u);
    uint32_t l;
    asm("cvt.rn.bf16x2.f32 %0, %1, %2;" : "=r"(l) : "f"(rb), "f"(ra));
    hi = h; lo = l;
}

// ----- 64B-row tiles (GEMM, BK=32) -----
__device__ __forceinline__ uint32_t sw_off(int row, int chunk) {
    return (uint32_t)(row * 64 + ((chunk ^ ((row >> 1) & 3)) << 4));
}
__device__ __forceinline__ void ldm_a(uint32_t tile, int row0, int kstep, int lane, uint32_t* r) {
    int row = row0 + (lane & 15);
    int ck  = kstep * 2 + ((lane >> 4) & 1);
    uint32_t addr = tile + sw_off(row, ck);
    asm volatile("ldmatrix.sync.aligned.m8n8.x4.shared.b16 {%0,%1,%2,%3}, [%4];"
                 : "=r"(r[0]), "=r"(r[1]), "=r"(r[2]), "=r"(r[3]) : "r"(addr));
}
__device__ __forceinline__ void ldm_b(uint32_t tile, int row0, int kstep, int lane, uint32_t* r) {
    int row = row0 + (lane & 7) + ((lane & 16) ? 8 : 0);
    int ck  = kstep * 2 + ((lane >> 3) & 1);
    uint32_t addr = tile + sw_off(row, ck);
    asm volatile("ldmatrix.sync.aligned.m8n8.x4.shared.b16 {%0,%1,%2,%3}, [%4];"
                 : "=r"(r[0]), "=r"(r[1]), "=r"(r[2]), "=r"(r[3]) : "r"(addr));
}

// ----- 128B-row tiles (attention, 64x64 bf16) -----
__device__ __forceinline__ uint32_t swoff128(int row, int ck) {
    return (uint32_t)(row * 128 + ((ck ^ (row & 7)) << 4));
}
__device__ __forceinline__ void ldm_a128(uint32_t tile, int row0, int t4, int lane, uint32_t* r) {
    int row = row0 + (lane & 15);
    int ck  = t4 * 2 + ((lane >> 4) & 1);
    uint32_t addr = tile + swoff128(row, ck);
    asm volatile("ldmatrix.sync.aligned.m8n8.x4.shared.b16 {%0,%1,%2,%3}, [%4];"
                 : "=r"(r[0]), "=r"(r[1]), "=r"(r[2]), "=r"(r[3]) : "r"(addr));
}
__device__ __forceinline__ void ldm_b128(uint32_t tile, int n0, int t4, int lane, uint32_t* r) {
    int row = n0 + (lane & 7) + ((lane >> 1) & 8);
    int ck  = t4 * 2 + ((lane >> 3) & 1);
    uint32_t addr = tile + swoff128(row, ck);
    asm volatile("ldmatrix.sync.aligned.m8n8.x4.shared.b16 {%0,%1,%2,%3}, [%4];"
                 : "=r"(r[0]), "=r"(r[1]), "=r"(r[2]), "=r"(r[3]) : "r"(addr));
}
__device__ __forceinline__ void ldm_vt128(uint32_t tile, int k0, int jp, int lane, uint32_t* r) {
    int row = k0 + (lane & 7) + (lane & 8);
    int ck  = jp * 2 + ((lane >> 4) & 1);
    uint32_t addr = tile + swoff128(row, ck);
    asm volatile("ldmatrix.sync.aligned.m8n8.x4.trans.shared.b16 {%0,%1,%2,%3}, [%4];"
                 : "=r"(r[0]), "=r"(r[1]), "=r"(r[2]), "=r"(r[3]) : "r"(addr));
}

// ---------------------------------------------------------------------------
// fp32 -> (hi, lo) bf16 split
// ---------------------------------------------------------------------------
__global__ __launch_bounds__(256) void f32_to_hilo(const float* __restrict__ in,
                                                   __nv_bfloat16* __restrict__ hi,
                                                   __nv_bfloat16* __restrict__ lo,
                                                   int n2)
{
    int i = blockIdx.x * blockDim.x + threadIdx.x;
    if (i >= n2) return;
    float2 v = ((const float2*)in)[i];
    uint32_t h, l;
    pack_hilo(v.x, v.y, h, l);
    ((uint32_t*)hi)[i] = h;
    ((uint32_t*)lo)[i] = l;
}

// ---------------------------------------------------------------------------
// Shared GEMM mainloop (bf16x3, NT, CTA 128x128, BK=32, double-buffered).
// Accumulates d[4][4][4] for warp tile (wm, wn). A = rows bm.., B = W rows bn..
// ---------------------------------------------------------------------------
#define STAGE_B   32768
#define GEMM_SMEM (2 * STAGE_B)
#define NCHUNK    32

__device__ __forceinline__ void gemm_mainloop(
    const __nv_bfloat16* __restrict__ Ahi, const __nv_bfloat16* __restrict__ Alo,
    const __nv_bfloat16* __restrict__ Bhi, const __nv_bfloat16* __restrict__ Blo,
    uint32_t sb, int bm, int bn, int t, int lane, int wm, int wn,
    float d[4][4][4])
{
    const int r0 = t >> 2,         c0 = t & 3;
    const int r1 = (t + 256) >> 2, c1 = t & 3;

    auto load_chunk = [&](int chunk, int st) {
        const size_t kb = (size_t)chunk * 32;
        const uint32_t s = sb + (uint32_t)st * STAGE_B;
        {
            uint32_t so = sw_off(r0, c0);
            const size_t ga = (size_t)(bm + r0) * D_ + kb + c0 * 8;
            const size_t gb = (size_t)(bn + r0) * D_ + kb + c0 * 8;
            CP_ASYNC_16(s + so,         Ahi + ga);
            CP_ASYNC_16(s + 8192  + so, Alo + ga);
            CP_ASYNC_16(s + 16384 + so, Bhi + gb);
            CP_ASYNC_16(s + 24576 + so, Blo + gb);
        }
        {
            uint32_t so = sw_off(r1, c1);
            const size_t ga = (size_t)(bm + r1) * D_ + kb + c1 * 8;
            const size_t gb = (size_t)(bn + r1) * D_ + kb + c1 * 8;
            CP_ASYNC_16(s + so,         Ahi + ga);
            CP_ASYNC_16(s + 8192  + so, Alo + ga);
            CP_ASYNC_16(s + 16384 + so, Bhi + gb);
            CP_ASYNC_16(s + 24576 + so, Blo + gb);
        }
        CP_COMMIT();
    };

    load_chunk(0, 0);

    for (int chunk = 0; chunk < NCHUNK; chunk++) {
        const int st = chunk & 1;
        if (chunk + 1 < NCHUNK) { load_chunk(chunk + 1, st ^ 1); cp_wait<1>(); }
        else                    { cp_wait<0>(); }
        __syncthreads();

        const uint32_t tAh = sb + (uint32_t)st * STAGE_B;
        const uint32_t tAl = tAh + 8192;
        const uint32_t tBh = tAh + 16384;
        const uint32_t tBl = tAh + 24576;

#pragma unroll
        for (int ks = 0; ks < 2; ks++) {
            uint32_t ah[4][4], al[4][4];
#pragma unroll
            for (int i = 0; i < 4; i++) {
                ldm_a(tAh, wm + i * 16, ks, lane, ah[i]);
                ldm_a(tAl, wm + i * 16, ks, lane, al[i]);
            }
            uint32_t bh[2][4], bl[2][4];
#pragma unroll
            for (int jp = 0; jp < 2; jp++) {
                ldm_b(tBh, wn + jp * 16, ks, lane, bh[jp]);
                ldm_b(tBl, wn + jp * 16, ks, lane, bl[jp]);
            }
#pragma unroll
            for (int i = 0; i < 4; i++)
#pragma unroll
                for (int j = 0; j < 4; j++) {
                    const uint32_t* ph = &bh[j >> 1][(j & 1) * 2];
                    const uint32_t* pl = &bl[j >> 1][(j & 1) * 2];
                    mma16816(d[i][j], ah[i], ph);
                    mma16816(d[i][j], ah[i], pl);
                    mma16816(d[i][j], al[i], ph);
                }
        }
        __syncthreads();
    }
}

// ---------------------------------------------------------------------------
// Fused QKV projection: grid.x = 24 (which = x/8 -> Q/K/V, n-tile = x%8).
// Consecutive blockIdx.x share the same A m-tile -> L2 reuse across weights.
// ---------------------------------------------------------------------------
__global__ __launch_bounds__(256) void gemm_qkv(
    const __nv_bfloat16* __restrict__ Ahi, const __nv_bfloat16* __restrict__ Alo,
    const __nv_bfloat16* __restrict__ Whi, const __nv_bfloat16* __restrict__ Wlo,
    __nv_bfloat16* __restrict__ Qhi, __nv_bfloat16* __restrict__ Qlo,
    __nv_bfloat16* __restrict__ Khi, __nv_bfloat16* __restrict__ Klo,
    __nv_bfloat16* __restrict__ Vhi, __nv_bfloat16* __restrict__ Vlo)
{
    extern __shared__ __align__(1024) char smem[];
    const uint32_t sb = smem_u32(smem);

    const int t     = threadIdx.x;
    const int lane  = t & 31;
    const int w     = t >> 5;
    const int wm    = (w >> 2) * 64;
    const int wn    = (w & 3) * 32;
    const int which = blockIdx.x >> 3;          // 0=Q, 1=K, 2=V
    const int bn    = (blockIdx.x & 7) * 128;
    const int bm    = blockIdx.y * 128;

    const __nv_bfloat16* Bhi = Whi + (size_t)which * (D_ * D_);
    const __nv_bfloat16* Blo = Wlo + (size_t)which * (D_ * D_);
    __nv_bfloat16* Chi = (which == 0) ? Qhi : (which == 1) ? Khi : Vhi;
    __nv_bfloat16* Clo = (which == 0) ? Qlo : (which == 1) ? Klo : Vlo;
    const float scale = (which == 0) ? 0.125f : 1.0f;

    float d[4][4][4];
#pragma unroll
    for (int i = 0; i < 4; i++)
#pragma unroll
        for (int j = 0; j < 4; j++)
#pragma unroll
            for (int e = 0; e < 4; e++) d[i][j][e] = 0.0f;

    gemm_mainloop(Ahi, Alo, Bhi, Blo, sb, bm, bn, t, lane, wm, wn, d);

#pragma unroll
    for (int i = 0; i < 4; i++) {
        const int row = bm + wm + i * 16 + (lane >> 2);
#pragma unroll
        for (int j = 0; j < 4; j++) {
            const int col = bn + wn + j * 8 + (lane & 3) * 2;
            uint32_t h01, l01, h23, l23;
            pack_hilo(d[i][j][0] * scale, d[i][j][1] * scale, h01, l01);
            pack_hilo(d[i][j][2] * scale, d[i][j][3] * scale, h23, l23);
            *(uint32_t*)(Chi + (size_t)row * D_ + col)       = h01;
            *(uint32_t*)(Clo + (size_t)row * D_ + col)       = l01;
            *(uint32_t*)(Chi + (size_t)(row + 8) * D_ + col) = h23;
            *(uint32_t*)(Clo + (size_t)(row + 8) * D_ + col) = l23;
        }
    }
}

// ---------------------------------------------------------------------------
// O-projection GEMM (fp32 output)
// ---------------------------------------------------------------------------
__global__ __launch_bounds__(256) void gemm_out(
    const __nv_bfloat16* __restrict__ Ahi, const __nv_bfloat16* __restrict__ Alo,
    const __nv_bfloat16* __restrict__ Bhi, const __nv_bfloat16* __restrict__ Blo,
    float* __restrict__ C)
{
    extern __shared__ __align__(1024) char smem[];
    const uint32_t sb = smem_u32(smem);

    const int t    = threadIdx.x;
    const int lane = t & 31;
    const int w    = t >> 5;
    const int wm   = (w >> 2) * 64;
    const int wn   = (w & 3) * 32;
    const int bm   = blockIdx.y * 128;
    const int bn   = blockIdx.x * 128;

    float d[4][4][4];
#pragma unroll
    for (int i = 0; i < 4; i++)
#pragma unroll
        for (int j = 0; j < 4; j++)
#pragma unroll
            for (int e = 0; e < 4; e++) d[i][j][e] = 0.0f;

    gemm_mainloop(Ahi, Alo, Bhi, Blo, sb, bm, bn, t, lane, wm, wn, d);

#pragma unroll
    for (int i = 0; i < 4; i++) {
        const int row = bm + wm + i * 16 + (lane >> 2);
#pragma unroll
        for (int j = 0; j < 4; j++) {
            const int col = bn + wn + j * 8 + (lane & 3) * 2;
            *(float2*)(C + (size_t)row * D_ + col)       = make_float2(d[i][j][0], d[i][j][1]);
            *(float2*)(C + (size_t)(row + 8) * D_ + col) = make_float2(d[i][j][2], d[i][j][3]);
        }
    }
}

// ---------------------------------------------------------------------------
// Flash attention on mma.sync (unchanged from R6 — validated)
// ---------------------------------------------------------------------------
#define ATT_SMEM 81920

__global__ __launch_bounds__(128) void attn_mma(
    const __nv_bfloat16* __restrict__ Qhi, const __nv_bfloat16* __restrict__ Qlo,
    const __nv_bfloat16* __restrict__ Khi, const __nv_bfloat16* __restrict__ Klo,
    const __nv_bfloat16* __restrict__ Vhi, const __nv_bfloat16* __restrict__ Vlo,
    __nv_bfloat16* __restrict__ AOhi, __nv_bfloat16* __restrict__ AOlo)
{
    extern __shared__ __align__(1024) char smem[];
    const uint32_t sb = smem_u32(smem);
    const int qt   = (int)gridDim.x - 1 - (int)blockIdx.x;
    const int h    = blockIdx.y;
    const int b    = blockIdx.z;
    const int tid  = threadIdx.x;
    const int lane = tid & 31;
    const int w    = tid >> 5;

    const size_t rowbase = (size_t)b * S_;
    const size_t cb      = (size_t)h * DK_;
    const int    q0      = qt * 64;

    const uint32_t sQh = sb, sQl = sb + 8192;

#pragma unroll
    for (int i = 0; i < 4; i++) {
        int p = tid + 128 * i; int r = p >> 3, ck = p & 7;
        size_t g = (rowbase + q0 + r) * D_ + cb + ck * 8;
        uint32_t so = swoff128(r, ck);
        CP_ASYNC_16(sQh + so, Qhi + g);
        CP_ASYNC_16(sQl + so, Qlo + g);
    }
    CP_COMMIT();

    auto load_kv = [&](int kt, int st) {
        uint32_t s = sb + 16384 + (uint32_t)st * 32768;
#pragma unroll
        for (int i = 0; i < 4; i++) {
            int p = tid + 128 * i; int r = p >> 3, ck = p & 7;
            uint32_t so = swoff128(r, ck);
            size_t g = (rowbase + kt * 64 + r) * D_ + cb + ck * 8;
            CP_ASYNC_16(s + so,         Khi + g);
            CP_ASYNC_16(s + 8192  + so, Klo + g);
            CP_ASYNC_16(s + 16384 + so, Vhi + g);
            CP_ASYNC_16(s + 24576 + so, Vlo + g);
        }
        CP_COMMIT();
    };
    load_kv(0, 0);

    cp_wait<1>();
    __syncthreads();

    uint32_t qh[4][4], ql[4][4];
#pragma unroll
    for (int t4 = 0; t4 < 4; t4++) {
        ldm_a128(sQh, w * 16, t4, lane, qh[t4]);
        ldm_a128(sQl, w * 16, t4, lane, ql[t4]);
    }

    float o[8][4];
#pragma unroll
    for (int j = 0; j < 8; j++)
#pragma unroll
        for (int e = 0; e < 4; e++) o[j][e] = 0.0f;
    float miA = -INFINITY, miB = -INFINITY, liA = 0.0f, liB = 0.0f;

    const int rA = w * 16 + (lane >> 2);
    const int cl = 2 * (lane & 3);

    for (int kt = 0; kt <= qt; kt++) {
        const int st = kt & 1;
        if (kt < qt) { load_kv(kt + 1, st ^ 1); cp_wait<1>(); }
        else         { cp_wait<0>(); }
        __syncthreads();

        const uint32_t Kh = sb + 16384 + (uint32_t)st * 32768;
        const uint32_t Kl = Kh + 8192, Vh = Kh + 16384, Vl = Kh + 24576;

        float s[8][4];
#pragma unroll
        for (int j = 0; j < 8; j++)
#pragma unroll
            for (int e = 0; e < 4; e++) s[j][e] = 0.0f;

#pragma unroll
        for (int t4 = 0; t4 < 4; t4++) {
#pragma unroll
            for (int jp = 0; jp < 4; jp++) {
                uint32_t kh[4], kl[4];
                ldm_b128(Kh, jp * 16, t4, lane, kh);
                ldm_b128(Kl, jp * 16, t4, lane, kl);
                mma16816(s[2 * jp],     qh[t4], kh);
                mma16816(s[2 * jp],     qh[t4], kl);
                mma16816(s[2 * jp],     ql[t4], kh);
                mma16816(s[2 * jp + 1], qh[t4], kh + 2);
                mma16816(s[2 * jp + 1], qh[t4], kl + 2);
                mma16816(s[2 * jp + 1], ql[t4], kh + 2);
            }
        }

        if (kt == qt) {
#pragma unroll
            for (int j = 0; j < 8; j++) {
                int c = 8 * j + cl;
                if (c     > rA)     s[j][0] = -INFINITY;
                if (c + 1 > rA)     s[j][1] = -INFINITY;
                if (c     > rA + 8) s[j][2] = -INFINITY;
                if (c + 1 > rA + 8) s[j][3] = -INFINITY;
            }
        }

        float mxA = s[0][0], mxB = s[0][2];
#pragma unroll
        for (int j = 0; j < 8; j++) {
            mxA = fmaxf(mxA, fmaxf(s[j][0], s[j][1]));
            mxB = fmaxf(mxB, fmaxf(s[j][2], s[j][3]));
        }
        mxA = fmaxf(mxA, __shfl_xor_sync(0xffffffffu, mxA, 1));
        mxA = fmaxf(mxA, __shfl_xor_sync(0xffffffffu, mxA, 2));
        mxB = fmaxf(mxB, __shfl_xor_sync(0xffffffffu, mxB, 1));
        mxB = fmaxf(mxB, __shfl_xor_sync(0xffffffffu, mxB, 2));

        float nA = fmaxf(miA, mxA), nB = fmaxf(miB, mxB);
        float aA = __expf(miA - nA), aB = __expf(miB - nB);
        miA = nA; miB = nB;
        liA *= aA; liB *= aB;
#pragma unroll
        for (int j = 0; j < 8; j++) {
            s[j][0] = __expf(s[j][0] - miA);
            s[j][1] = __expf(s[j][1] - miA);
            s[j][2] = __expf(s[j][2] - miB);
            s[j][3] = __expf(s[j][3] - miB);
            liA += s[j][0] + s[j][1];
            liB += s[j][2] + s[j][3];
            o[j][0] *= aA; o[j][1] *= aA; o[j][2] *= aB; o[j][3] *= aB;
        }

        uint32_t ph[4][4], pl[4][4];
#pragma unroll
        for (int t4 = 0; t4 < 4; t4++) {
            pack_hilo(s[2 * t4][0],     s[2 * t4][1],     ph[t4][0], pl[t4][0]);
            pack_hilo(s[2 * t4][2],     s[2 * t4][3],     ph[t4][1], pl[t4][1]);
            pack_hilo(s[2 * t4 + 1][0], s[2 * t4 + 1][1], ph[t4][2], pl[t4][2]);
            pack_hilo(s[2 * t4 + 1][2], s[2 * t4 + 1][3], ph[t4][3], pl[t4][3]);
        }

#pragma unroll
        for (int t4 = 0; t4 < 4; t4++) {
#pragma unroll
            for (int jp = 0; jp < 4; jp++) {
                uint32_t vh[4], vl[4];
                ldm_vt128(Vh, t4 * 16, jp, lane, vh);
                ldm_vt128(Vl, t4 * 16, jp, lane, vl);
                mma16816(o[2 * jp],     ph[t4], vh);
                mma16816(o[2 * jp],     pl[t4], vh);
                mma16816(o[2 * jp],     ph[t4], vl);
                mma16816(o[2 * jp + 1], ph[t4], vh + 2);
                mma16816(o[2 * jp + 1], pl[t4], vh + 2);
                mma16816(o[2 * jp + 1], ph[t4], vl + 2);
            }
        }
        __syncthreads();
    }

    liA += __shfl_xor_sync(0xffffffffu, liA, 1);
    liA += __shfl_xor_sync(0xffffffffu, liA, 2);
    liB += __shfl_xor_sync(0xffffffffu, liB, 1);
    liB += __shfl_xor_sync(0xffffffffu, liB, 2);
    const float invA = 1.0f / liA, invB = 1.0f / liB;

    const size_t gA = (rowbase + q0 + rA) * D_ + cb + cl;
#pragma unroll
    for (int j = 0; j < 8; j++) {
        uint32_t hA, lA, hB, lB;
        pack_hilo(o[j][0] * invA, o[j][1] * invA, hA, lA);
        pack_hilo(o[j][2] * invB, o[j][3] * invB, hB, lB);
        *(uint32_t*)(AOhi + gA + 8 * j)           = hA;
        *(uint32_t*)(AOlo + gA + 8 * j)           = lA;
        *(uint32_t*)(AOhi + gA + 8 * j + 8 * D_)  = hB;
        *(uint32_t*)(AOlo + gA + 8 * j + 8 * D_)  = lB;
    }
}

// ---------------------------------------------------------------------------
// kernel_launch
// ---------------------------------------------------------------------------
extern "C" void kernel_launch(void* const* d_in, const int* in_sizes, int n_in,
                              void* d_out, int out_size)
{
    const float* x  = (const float*)d_in[0];
    const float* wp[4] = { (const float*)d_in[1], (const float*)d_in[2],
                           (const float*)d_in[3], (const float*)d_in[4] };
    float* out = (float*)d_out;

    __nv_bfloat16 *xhi, *xlo, *qhi, *qlo, *khi, *klo, *vhi, *vlo, *aohi, *aolo, *whi, *wlo;
    cudaGetSymbolAddress((void**)&xhi,  g_xhi);
    cudaGetSymbolAddress((void**)&xlo,  g_xlo);
    cudaGetSymbolAddress((void**)&qhi,  g_qhi);
    cudaGetSymbolAddress((void**)&qlo,  g_qlo);
    cudaGetSymbolAddress((void**)&khi,  g_khi);
    cudaGetSymbolAddress((void**)&klo,  g_klo);
    cudaGetSymbolAddress((void**)&vhi,  g_vhi);
    cudaGetSymbolAddress((void**)&vlo,  g_vlo);
    cudaGetSymbolAddress((void**)&aohi, g_aohi);
    cudaGetSymbolAddress((void**)&aolo, g_aolo);
    cudaGetSymbolAddress((void**)&whi,  g_whi);
    cudaGetSymbolAddress((void**)&wlo,  g_wlo);

    const int n2x = M_ * D_ / 2;
    const int n2w = D_ * D_ / 2;
    f32_to_hilo<<<(n2x + 255) / 256, 256>>>(x, xhi, xlo, n2x);
    for (int i = 0; i < 4; i++)
        f32_to_hilo<<<(n2w + 255) / 256, 256>>>(wp[i], whi + (size_t)i * D_ * D_,
                                                wlo + (size_t)i * D_ * D_, n2w);

    cudaFuncSetAttribute(gemm_qkv, cudaFuncAttributeMaxDynamicSharedMemorySize, GEMM_SMEM);
    cudaFuncSetAttribute(gemm_out, cudaFuncAttributeMaxDynamicSharedMemorySize, GEMM_SMEM);
    cudaFuncSetAttribute(attn_mma, cudaFuncAttributeMaxDynamicSharedMemorySize, ATT_SMEM);

    gemm_qkv<<<dim3(24, M_ / 128), 256, GEMM_SMEM>>>(xhi, xlo, whi, wlo,
                                                     qhi, qlo, khi, klo, vhi, vlo);

    attn_mma<<<dim3(S_ / 64, H_, B_), 128, ATT_SMEM>>>(qhi, qlo, khi, klo, vhi, vlo, aohi, aolo);

    gemm_out<<<dim3(D_ / 128, M_ / 128), 256, GEMM_SMEM>>>(
        aohi, aolo, whi + 3 * (size_t)(D_ * D_), wlo + 3 * (size_t)(D_ * D_), out);
}